// round 1
// baseline (speedup 1.0000x reference)
#include <cuda_runtime.h>
#include <math.h>

// Problem constants (fixed shapes per reference)
#define Bb 2
#define Nn 4096
#define Dd 512
#define Hh 8
#define Pp 9
#define HDm 64
#define GW 256   // grid width  (w)
#define GH 16    // grid height (h)
#define Mrows (Bb*Nn)   // 8192

// Scratch (device globals — no allocation allowed)
__device__ float g_q  [Mrows * Dd];          // 16 MB
__device__ float g_off[Mrows * Hh * Pp * 2]; // 4.5 MB
__device__ float g_kv [Mrows * 2 * Dd];      // 32 MB
__device__ float g_att[Mrows * Dd];          // 16 MB

// -------------------------------------------------------------------------
// Y[M, Nout] = X[M, K] @ W[Nout, K]^T + bias  (ACT==1 -> tanh)
// 64x64 block tile, BK=16, 256 threads, 4x4 microtile.
// -------------------------------------------------------------------------
template <int ACT>
__global__ void gemm_xwt(const float* __restrict__ X, const float* __restrict__ W,
                         const float* __restrict__ bias, float* __restrict__ Y,
                         int M, int Nout, int K) {
    __shared__ float Xs[16][65];
    __shared__ float Ws[16][65];

    const int tid = threadIdx.x;
    const int tx = tid & 15;        // 0..15 (n dir)
    const int ty = tid >> 4;        // 0..15 (m dir)
    const int m0 = blockIdx.y * 64;
    const int n0 = blockIdx.x * 64;

    const int lk = tid & 15;        // k within tile
    const int lr = tid >> 4;        // row base (strided by 16)

    float acc[4][4] = {};

    for (int k0 = 0; k0 < K; k0 += 16) {
#pragma unroll
        for (int i = 0; i < 4; i++) {
            int m = lr + i * 16;
            Xs[lk][m] = X[(size_t)(m0 + m) * K + k0 + lk];
        }
#pragma unroll
        for (int i = 0; i < 4; i++) {
            int nn = lr + i * 16;
            int gn = n0 + nn;
            Ws[lk][nn] = (gn < Nout) ? W[(size_t)gn * K + k0 + lk] : 0.0f;
        }
        __syncthreads();

#pragma unroll
        for (int kk = 0; kk < 16; kk++) {
            float a[4], bvals[4];
#pragma unroll
            for (int i = 0; i < 4; i++) a[i] = Xs[kk][ty * 4 + i];
#pragma unroll
            for (int j = 0; j < 4; j++) bvals[j] = Ws[kk][tx * 4 + j];
#pragma unroll
            for (int i = 0; i < 4; i++)
#pragma unroll
                for (int j = 0; j < 4; j++)
                    acc[i][j] = fmaf(a[i], bvals[j], acc[i][j]);
        }
        __syncthreads();
    }

#pragma unroll
    for (int i = 0; i < 4; i++) {
        int m = m0 + ty * 4 + i;
#pragma unroll
        for (int j = 0; j < 4; j++) {
            int nn = n0 + tx * 4 + j;
            if (nn < Nout) {
                float v = acc[i][j] + bias[nn];
                if (ACT == 1) v = tanhf(v);
                Y[(size_t)m * Nout + nn] = v;
            }
        }
    }
}

// -------------------------------------------------------------------------
// One warp per (b, n, h): bilinear-sample k/v at 9 deformable points,
// logits = q.sk * HD^-0.5, softmax over P, out = sum attn*sv.
// Lane L owns dims L and L+32 of the 64-dim head slice.
// -------------------------------------------------------------------------
__global__ void attn_kernel(const float* __restrict__ q,
                            const float* __restrict__ off,
                            const float* __restrict__ kv,
                            float* __restrict__ out) {
    int gw   = (blockIdx.x * blockDim.x + threadIdx.x) >> 5;
    int lane = threadIdx.x & 31;
    if (gw >= Bb * Nn * Hh) return;

    int hh = gw & (Hh - 1);
    int n  = (gw >> 3) & (Nn - 1);
    int b  = gw >> 15;

    size_t row = (size_t)(b * Nn + n);
    const float* qp = q + row * Dd + hh * HDm;
    float q0 = qp[lane];
    float q1 = qp[lane + 32];

    float bx = (float)(n & (GW - 1));
    float by = (float)(n >> 8);

    const float* offp = off + row * (Hh * Pp * 2) + hh * Pp * 2;
    const float* kvb  = kv + (size_t)b * Nn * (2 * Dd);

    float lg[Pp], sv0[Pp], sv1[Pp];

#pragma unroll
    for (int p = 0; p < Pp; p++) {
        float sx = bx + 4.0f * offp[2 * p];
        float sy = by + 4.0f * offp[2 * p + 1];
        float x0f = floorf(sx), y0f = floorf(sy);
        int   x0 = (int)x0f,  y0 = (int)y0f;
        float wx1 = sx - x0f, wy1 = sy - y0f;
        float wx0 = 1.0f - wx1, wy0 = 1.0f - wy1;

        float sk0 = 0.f, sk1 = 0.f, v0 = 0.f, v1 = 0.f;
#pragma unroll
        for (int c = 0; c < 4; c++) {
            int   xi = x0 + (c & 1);
            int   yi = y0 + (c >> 1);
            float wgt = ((c & 1) ? wx1 : wx0) * ((c >> 1) ? wy1 : wy0);
            if (xi >= 0 && xi < GW && yi >= 0 && yi < GH) {
                const float* ptr = kvb + (size_t)(yi * GW + xi) * (2 * Dd) + hh * HDm;
                sk0 = fmaf(wgt, ptr[lane],            sk0);
                sk1 = fmaf(wgt, ptr[lane + 32],       sk1);
                v0  = fmaf(wgt, ptr[Dd + lane],       v0);
                v1  = fmaf(wgt, ptr[Dd + lane + 32],  v1);
            }
        }
        float d = q0 * sk0 + q1 * sk1;
#pragma unroll
        for (int s = 16; s > 0; s >>= 1)
            d += __shfl_xor_sync(0xffffffffu, d, s);
        lg[p]  = d * 0.125f;   // HD^-0.5 = 1/8
        sv0[p] = v0;
        sv1[p] = v1;
    }

    float mx = lg[0];
#pragma unroll
    for (int p = 1; p < Pp; p++) mx = fmaxf(mx, lg[p]);
    float se = 0.f, wp[Pp];
#pragma unroll
    for (int p = 0; p < Pp; p++) { wp[p] = __expf(lg[p] - mx); se += wp[p]; }
    float inv = 1.0f / se;

    float o0 = 0.f, o1 = 0.f;
#pragma unroll
    for (int p = 0; p < Pp; p++) { o0 = fmaf(wp[p], sv0[p], o0); o1 = fmaf(wp[p], sv1[p], o1); }

    float* op = out + row * Dd + hh * HDm;
    op[lane]      = o0 * inv;
    op[lane + 32] = o1 * inv;
}

// -------------------------------------------------------------------------
extern "C" void kernel_launch(void* const* d_in, const int* in_sizes, int n_in,
                              void* d_out, int out_size) {
    const float* x    = (const float*)d_in[0];
    const float* Wq   = (const float*)d_in[1];
    const float* bq   = (const float*)d_in[2];
    const float* Woff = (const float*)d_in[3];
    const float* boff = (const float*)d_in[4];
    const float* Wkv  = (const float*)d_in[5];
    const float* bkv  = (const float*)d_in[6];
    const float* Wo   = (const float*)d_in[7];
    const float* bo   = (const float*)d_in[8];
    float* out = (float*)d_out;

    float *qb, *offb, *kvb, *attb;
    cudaGetSymbolAddress((void**)&qb,   g_q);
    cudaGetSymbolAddress((void**)&offb, g_off);
    cudaGetSymbolAddress((void**)&kvb,  g_kv);
    cudaGetSymbolAddress((void**)&attb, g_att);

    // q = x @ Wq^T + bq                       (8192 x 512)
    gemm_xwt<0><<<dim3(512 / 64, Mrows / 64), 256>>>(x, Wq, bq, qb, Mrows, 512, Dd);
    // off = tanh(x @ Woff^T + boff)           (8192 x 144)
    gemm_xwt<1><<<dim3(3, Mrows / 64), 256>>>(x, Woff, boff, offb, Mrows, Hh * Pp * 2, Dd);
    // kv = x @ Wkv^T + bkv                    (8192 x 1024)
    gemm_xwt<0><<<dim3(1024 / 64, Mrows / 64), 256>>>(x, Wkv, bkv, kvb, Mrows, 1024, Dd);

    // deformable sampling + attention         (B*N*H warps)
    int total_warps = Bb * Nn * Hh;            // 65536
    attn_kernel<<<total_warps / 4, 128>>>(qb, offb, kvb, attb);

    // out = att @ Wo^T + bo                   (8192 x 512) -> d_out
    gemm_xwt<0><<<dim3(512 / 64, Mrows / 64), 256>>>(attb, Wo, bo, out, Mrows, 512, Dd);
}

// round 2
// speedup vs baseline: 1.8052x; 1.8052x over previous
#include <cuda_runtime.h>
#include <cuda_bf16.h>
#include <math.h>

// Problem constants (fixed shapes per reference)
#define Bb 2
#define Nn 4096
#define Dd 512
#define Hh 8
#define Pp 9
#define HDm 64
#define GW 256   // grid width  (w)
#define GH 16    // grid height (h)
#define Mrows (Bb*Nn)   // 8192
#define Kdim 512

// Scratch (device globals — no allocation allowed)
__device__ float g_q  [Mrows * Dd];          // 16 MB
__device__ float g_off[Mrows * Hh * Pp * 2]; // 4.5 MB
__device__ float g_kv [Mrows * 2 * Dd];      // 32 MB
__device__ float g_att[Mrows * Dd];          // 16 MB

// -------------------------------------------------------------------------
// bf16 split helpers
// -------------------------------------------------------------------------
__device__ __forceinline__ void split2(float f0, float f1, unsigned& hi, unsigned& lo) {
    __nv_bfloat16 h0 = __float2bfloat16(f0);
    __nv_bfloat16 h1 = __float2bfloat16(f1);
    float r0 = f0 - __bfloat162float(h0);
    float r1 = f1 - __bfloat162float(h1);
    __nv_bfloat162 H = __halves2bfloat162(h0, h1);
    __nv_bfloat162 L = __halves2bfloat162(__float2bfloat16(r0), __float2bfloat16(r1));
    hi = *reinterpret_cast<unsigned*>(&H);
    lo = *reinterpret_cast<unsigned*>(&L);
}

__device__ __forceinline__ void mma16816(float c[4],
                                         unsigned a0, unsigned a1, unsigned a2, unsigned a3,
                                         unsigned b0, unsigned b1) {
    asm volatile(
        "mma.sync.aligned.m16n8k16.row.col.f32.bf16.bf16.f32 "
        "{%0,%1,%2,%3},{%4,%5,%6,%7},{%8,%9},{%0,%1,%2,%3};"
        : "+f"(c[0]), "+f"(c[1]), "+f"(c[2]), "+f"(c[3])
        : "r"(a0), "r"(a1), "r"(a2), "r"(a3), "r"(b0), "r"(b1));
}

// -------------------------------------------------------------------------
// Y[M, Nout] = X[M, 512] @ W[Nout, 512]^T + bias  (ACT==1 -> tanh)
// Tensor-core bf16-split GEMM. Block tile 128x64, BK=16, 256 threads.
// Warp layout 2(M) x 4(N); warp tile 64x16 = 4x2 mma(m16n8k16) tiles.
// Each mma tile does 3 HMMAs: Ahi*Bhi + Ahi*Blo + Alo*Bhi.
// -------------------------------------------------------------------------
template <int ACT>
__global__ __launch_bounds__(256) void gemm_bf16split(
        const float* __restrict__ X, const float* __restrict__ W,
        const float* __restrict__ bias, float* __restrict__ Y, int Nout) {
    __shared__ unsigned Ahi[128][8], Alo[128][8];   // [m][k-pair] packed bf16x2
    __shared__ unsigned Bhi[64][8],  Blo[64][8];    // [n][k-pair]

    const int t    = threadIdx.x;
    const int m0   = blockIdx.y * 128;
    const int n0   = blockIdx.x * 64;
    const int wid  = t >> 5;
    const int lane = t & 31;
    const int gid  = lane >> 2;   // 0..7
    const int tg   = lane & 3;    // 0..3
    const int wm   = wid & 1;     // 2 warps in M
    const int wn   = wid >> 1;    // 4 warps in N

    // global load assignments
    const int ar = t >> 1;            // 0..127 (A row)
    const int ak = (t & 1) * 8;       // 0 or 8 (A k offset)
    const int br = t >> 2;            // 0..63 (B row)
    const int bk = (t & 3) * 4;       // 0,4,8,12 (B k offset)
    const float* Xp = X + (size_t)(m0 + ar) * Kdim + ak;
    const bool bvalid = (n0 + br) < Nout;
    const float* Wp = W + (size_t)(n0 + br) * Kdim + bk;

    float c[4][2][4] = {};

    for (int k0 = 0; k0 < Kdim; k0 += 16) {
        // ---- fill smem (split once per element) ----
        float4 av0 = *reinterpret_cast<const float4*>(Xp + k0);
        float4 av1 = *reinterpret_cast<const float4*>(Xp + k0 + 4);
        unsigned h, l;
        int ac = ak >> 1;
        split2(av0.x, av0.y, h, l); Ahi[ar][ac + 0] = h; Alo[ar][ac + 0] = l;
        split2(av0.z, av0.w, h, l); Ahi[ar][ac + 1] = h; Alo[ar][ac + 1] = l;
        split2(av1.x, av1.y, h, l); Ahi[ar][ac + 2] = h; Alo[ar][ac + 2] = l;
        split2(av1.z, av1.w, h, l); Ahi[ar][ac + 3] = h; Alo[ar][ac + 3] = l;

        float4 bv = bvalid ? *reinterpret_cast<const float4*>(Wp + k0)
                           : make_float4(0.f, 0.f, 0.f, 0.f);
        int bc = bk >> 1;
        split2(bv.x, bv.y, h, l); Bhi[br][bc + 0] = h; Blo[br][bc + 0] = l;
        split2(bv.z, bv.w, h, l); Bhi[br][bc + 1] = h; Blo[br][bc + 1] = l;
        __syncthreads();

        // ---- B fragments (2 n-tiles) ----
        unsigned bh[2][2], bl[2][2];
#pragma unroll
        for (int j = 0; j < 2; j++) {
            int nrow = wn * 16 + j * 8 + gid;
            bh[j][0] = Bhi[nrow][tg];     bh[j][1] = Bhi[nrow][tg + 4];
            bl[j][0] = Blo[nrow][tg];     bl[j][1] = Blo[nrow][tg + 4];
        }

        // ---- A fragments per m-tile + mma ----
#pragma unroll
        for (int i = 0; i < 4; i++) {
            int mrow = wm * 64 + i * 16 + gid;
            unsigned ah0 = Ahi[mrow][tg],     ah1 = Ahi[mrow + 8][tg];
            unsigned ah2 = Ahi[mrow][tg + 4], ah3 = Ahi[mrow + 8][tg + 4];
            unsigned al0 = Alo[mrow][tg],     al1 = Alo[mrow + 8][tg];
            unsigned al2 = Alo[mrow][tg + 4], al3 = Alo[mrow + 8][tg + 4];
#pragma unroll
            for (int j = 0; j < 2; j++) {
                mma16816(c[i][j], ah0, ah1, ah2, ah3, bh[j][0], bh[j][1]);
                mma16816(c[i][j], ah0, ah1, ah2, ah3, bl[j][0], bl[j][1]);
                mma16816(c[i][j], al0, al1, al2, al3, bh[j][0], bh[j][1]);
            }
        }
        __syncthreads();
    }

    // ---- epilogue: bias (+tanh), guarded store ----
#pragma unroll
    for (int i = 0; i < 4; i++) {
        int m = m0 + wm * 64 + i * 16 + gid;
#pragma unroll
        for (int j = 0; j < 2; j++) {
            int nn = n0 + wn * 16 + j * 8 + tg * 2;
#pragma unroll
            for (int rr = 0; rr < 2; rr++) {         // row: gid, gid+8
                int mm = m + rr * 8;
#pragma unroll
                for (int cc = 0; cc < 2; cc++) {     // col: nn, nn+1
                    int nc = nn + cc;
                    if (nc < Nout) {
                        float v = c[i][j][rr * 2 + cc] + bias[nc];
                        if (ACT == 1) v = tanhf(v);
                        Y[(size_t)mm * Nout + nc] = v;
                    }
                }
            }
        }
    }
}

// -------------------------------------------------------------------------
// One warp per (b, n, h): bilinear-sample k/v at 9 deformable points,
// logits = q.sk * HD^-0.5, softmax over P, out = sum attn*sv.
// -------------------------------------------------------------------------
__global__ void attn_kernel(const float* __restrict__ q,
                            const float* __restrict__ off,
                            const float* __restrict__ kv,
                            float* __restrict__ out) {
    int gw   = (blockIdx.x * blockDim.x + threadIdx.x) >> 5;
    int lane = threadIdx.x & 31;
    if (gw >= Bb * Nn * Hh) return;

    int hh = gw & (Hh - 1);
    int n  = (gw >> 3) & (Nn - 1);
    int b  = gw >> 15;

    size_t row = (size_t)(b * Nn + n);
    const float* qp = q + row * Dd + hh * HDm;
    float q0 = qp[lane];
    float q1 = qp[lane + 32];

    float bx = (float)(n & (GW - 1));
    float by = (float)(n >> 8);

    const float* offp = off + row * (Hh * Pp * 2) + hh * Pp * 2;
    const float* kvb  = kv + (size_t)b * Nn * (2 * Dd);

    float lg[Pp], sv0[Pp], sv1[Pp];

#pragma unroll
    for (int p = 0; p < Pp; p++) {
        float sx = bx + 4.0f * offp[2 * p];
        float sy = by + 4.0f * offp[2 * p + 1];
        float x0f = floorf(sx), y0f = floorf(sy);
        int   x0 = (int)x0f,  y0 = (int)y0f;
        float wx1 = sx - x0f, wy1 = sy - y0f;
        float wx0 = 1.0f - wx1, wy0 = 1.0f - wy1;

        float sk0 = 0.f, sk1 = 0.f, v0 = 0.f, v1 = 0.f;
#pragma unroll
        for (int cc = 0; cc < 4; cc++) {
            int   xi = x0 + (cc & 1);
            int   yi = y0 + (cc >> 1);
            float wgt = ((cc & 1) ? wx1 : wx0) * ((cc >> 1) ? wy1 : wy0);
            if (xi >= 0 && xi < GW && yi >= 0 && yi < GH) {
                const float* ptr = kvb + (size_t)(yi * GW + xi) * (2 * Dd) + hh * HDm;
                sk0 = fmaf(wgt, ptr[lane],            sk0);
                sk1 = fmaf(wgt, ptr[lane + 32],       sk1);
                v0  = fmaf(wgt, ptr[Dd + lane],       v0);
                v1  = fmaf(wgt, ptr[Dd + lane + 32],  v1);
            }
        }
        float d = q0 * sk0 + q1 * sk1;
#pragma unroll
        for (int s = 16; s > 0; s >>= 1)
            d += __shfl_xor_sync(0xffffffffu, d, s);
        lg[p]  = d * 0.125f;   // HD^-0.5 = 1/8
        sv0[p] = v0;
        sv1[p] = v1;
    }

    float mx = lg[0];
#pragma unroll
    for (int p = 1; p < Pp; p++) mx = fmaxf(mx, lg[p]);
    float se = 0.f, wp[Pp];
#pragma unroll
    for (int p = 0; p < Pp; p++) { wp[p] = __expf(lg[p] - mx); se += wp[p]; }
    float inv = 1.0f / se;

    float o0 = 0.f, o1 = 0.f;
#pragma unroll
    for (int p = 0; p < Pp; p++) { o0 = fmaf(wp[p], sv0[p], o0); o1 = fmaf(wp[p], sv1[p], o1); }

    float* op = out + row * Dd + hh * HDm;
    op[lane]      = o0 * inv;
    op[lane + 32] = o1 * inv;
}

// -------------------------------------------------------------------------
extern "C" void kernel_launch(void* const* d_in, const int* in_sizes, int n_in,
                              void* d_out, int out_size) {
    const float* x    = (const float*)d_in[0];
    const float* Wq   = (const float*)d_in[1];
    const float* bq   = (const float*)d_in[2];
    const float* Woff = (const float*)d_in[3];
    const float* boff = (const float*)d_in[4];
    const float* Wkv  = (const float*)d_in[5];
    const float* bkv  = (const float*)d_in[6];
    const float* Wo   = (const float*)d_in[7];
    const float* bo   = (const float*)d_in[8];
    float* out = (float*)d_out;

    float *qb, *offb, *kvb, *attb;
    cudaGetSymbolAddress((void**)&qb,   g_q);
    cudaGetSymbolAddress((void**)&offb, g_off);
    cudaGetSymbolAddress((void**)&kvb,  g_kv);
    cudaGetSymbolAddress((void**)&attb, g_att);

    // q = x @ Wq^T + bq                       (8192 x 512)
    gemm_bf16split<0><<<dim3(512 / 64, Mrows / 128), 256>>>(x, Wq, bq, qb, 512);
    // off = tanh(x @ Woff^T + boff)           (8192 x 144)
    gemm_bf16split<1><<<dim3(3, Mrows / 128), 256>>>(x, Woff, boff, offb, Hh * Pp * 2);
    // kv = x @ Wkv^T + bkv                    (8192 x 1024)
    gemm_bf16split<0><<<dim3(1024 / 64, Mrows / 128), 256>>>(x, Wkv, bkv, kvb, 1024);

    // deformable sampling + attention         (B*N*H warps)
    int total_warps = Bb * Nn * Hh;            // 65536
    attn_kernel<<<total_warps / 4, 128>>>(qb, offb, kvb, attb);

    // out = att @ Wo^T + bo                   (8192 x 512) -> d_out
    gemm_bf16split<0><<<dim3(512 / 64, Mrows / 128), 256>>>(attb, Wo, bo, out, 512);
}

// round 3
// speedup vs baseline: 2.6483x; 1.4670x over previous
#include <cuda_runtime.h>
#include <cuda_bf16.h>
#include <math.h>

// Problem constants (fixed shapes per reference)
#define Bb 2
#define Nn 4096
#define Dd 512
#define Hh 8
#define Pp 9
#define HDm 64
#define GW 256
#define GH 16
#define Mrows (Bb*Nn)   // 8192
#define Kdim 512

// ------------------------- scratch (device globals) -----------------------
__device__ float g_q  [Mrows * Dd];
__device__ float g_off[Mrows * Hh * Pp * 2];
__device__ float g_kv [Mrows * 2 * Dd];

__device__ __nv_bfloat16 g_xhi[Mrows * Kdim],  g_xlo[Mrows * Kdim];
__device__ __nv_bfloat16 g_wqhi[512 * Kdim],   g_wqlo[512 * Kdim];
__device__ __nv_bfloat16 g_wfhi[256 * Kdim],   g_wflo[256 * Kdim];   // Woff padded 144->256
__device__ __nv_bfloat16 g_wkhi[1024 * Kdim],  g_wklo[1024 * Kdim];
__device__ __nv_bfloat16 g_wohi[512 * Kdim],   g_wolo[512 * Kdim];
__device__ __nv_bfloat16 g_ahi[Mrows * Kdim],  g_alo[Mrows * Kdim];  // att hi/lo

// ------------------------- fp32 -> bf16 hi/lo split ------------------------
__global__ void convert_split(const float* __restrict__ src,
                              __nv_bfloat16* __restrict__ hi,
                              __nv_bfloat16* __restrict__ lo,
                              int n_src, int n_dst) {
    int i = blockIdx.x * blockDim.x + threadIdx.x;
    if (i >= n_dst) return;
    float v = (i < n_src) ? src[i] : 0.0f;
    __nv_bfloat16 h = __float2bfloat16(v);
    hi[i] = h;
    lo[i] = __float2bfloat16(v - __bfloat162float(h));
}

// ------------------------- mma + cp.async helpers --------------------------
__device__ __forceinline__ void mma16816(float c[4],
                                         unsigned a0, unsigned a1, unsigned a2, unsigned a3,
                                         unsigned b0, unsigned b1) {
    asm volatile(
        "mma.sync.aligned.m16n8k16.row.col.f32.bf16.bf16.f32 "
        "{%0,%1,%2,%3},{%4,%5,%6,%7},{%8,%9},{%0,%1,%2,%3};"
        : "+f"(c[0]), "+f"(c[1]), "+f"(c[2]), "+f"(c[3])
        : "r"(a0), "r"(a1), "r"(a2), "r"(a3), "r"(b0), "r"(b1));
}

__device__ __forceinline__ void cpa16(unsigned* smem_ptr, const void* gmem) {
    unsigned s = (unsigned)__cvta_generic_to_shared(smem_ptr);
    asm volatile("cp.async.cg.shared.global [%0], [%1], 16;" :: "r"(s), "l"(gmem));
}

// ---------------------------------------------------------------------------
// Y[M, Nout] = A[M,512] @ B[Nb,512]^T + bias  (pre-split bf16 hi/lo inputs)
// Block 128x128, BK=32, 2-stage cp.async pipeline, 256 threads (8 warps 2x4).
// Warp tile 64x32 -> 4x4 m16n8k16 tiles, 3 split-MMAs each.
// smem rows: 16 packed bf16x2 words + pad 4 => stride 20 (conflict-free).
// ---------------------------------------------------------------------------
#define SROW 20
#define STAGE_W (128 * SROW)          // words per tile-plane per stage

template <int ACT>
__global__ __launch_bounds__(256) void gemm_pre(
        const __nv_bfloat16* __restrict__ Ahi, const __nv_bfloat16* __restrict__ Alo,
        const __nv_bfloat16* __restrict__ Bhi, const __nv_bfloat16* __restrict__ Blo,
        const float* __restrict__ bias, float* __restrict__ Y, int Nout) {
    extern __shared__ unsigned sm[];
    unsigned* sAh = sm;                    // [2][128][SROW]
    unsigned* sAl = sm + 2 * STAGE_W;
    unsigned* sBh = sm + 4 * STAGE_W;
    unsigned* sBl = sm + 6 * STAGE_W;

    const int t    = threadIdx.x;
    const int m0   = blockIdx.y * 128;
    const int n0   = blockIdx.x * 128;
    const int wid  = t >> 5;
    const int lane = t & 31;
    const int gid  = lane >> 2;
    const int tg   = lane & 3;
    const int wm   = wid & 1;     // 2 warps in M
    const int wn   = wid >> 1;    // 4 warps in N

    // load assignment: row = t>>1 (0..127), chunks (t&1)*2, +1  (16B chunks of 8 bf16)
    const int lrow = t >> 1;
    const int lcb  = (t & 1) * 2;
    const __nv_bfloat16* gAh = Ahi + (size_t)(m0 + lrow) * Kdim;
    const __nv_bfloat16* gAl = Alo + (size_t)(m0 + lrow) * Kdim;
    const __nv_bfloat16* gBh = Bhi + (size_t)(n0 + lrow) * Kdim;
    const __nv_bfloat16* gBl = Blo + (size_t)(n0 + lrow) * Kdim;

    float c[4][4][4] = {};

    const int NT = Kdim / 32;   // 16 k-tiles

    // ---- issue loads for a stage ----
    auto issue = [&](int stage, int kt) {
        int k0 = kt * 32;
        unsigned* dA = sAh + stage * STAGE_W + lrow * SROW;
        unsigned* dAl2 = sAl + stage * STAGE_W + lrow * SROW;
        unsigned* dB = sBh + stage * STAGE_W + lrow * SROW;
        unsigned* dBl2 = sBl + stage * STAGE_W + lrow * SROW;
#pragma unroll
        for (int cc = 0; cc < 2; cc++) {
            int ch = lcb + cc;
            cpa16(dA   + ch * 4, gAh + k0 + ch * 8);
            cpa16(dAl2 + ch * 4, gAl + k0 + ch * 8);
            cpa16(dB   + ch * 4, gBh + k0 + ch * 8);
            cpa16(dBl2 + ch * 4, gBl + k0 + ch * 8);
        }
        asm volatile("cp.async.commit_group;");
    };

    issue(0, 0);

    for (int kt = 0; kt < NT; kt++) {
        int cur = kt & 1;
        if (kt + 1 < NT) {
            issue(cur ^ 1, kt + 1);
            asm volatile("cp.async.wait_group 1;");
        } else {
            asm volatile("cp.async.wait_group 0;");
        }
        __syncthreads();

        const unsigned* pAh = sAh + cur * STAGE_W;
        const unsigned* pAl = sAl + cur * STAGE_W;
        const unsigned* pBh = sBh + cur * STAGE_W;
        const unsigned* pBl = sBl + cur * STAGE_W;

#pragma unroll
        for (int ks = 0; ks < 2; ks++) {
            unsigned bh[4][2], bl[4][2];
#pragma unroll
            for (int j = 0; j < 4; j++) {
                int base = (wn * 32 + j * 8 + gid) * SROW + ks * 8;
                bh[j][0] = pBh[base + tg];  bh[j][1] = pBh[base + tg + 4];
                bl[j][0] = pBl[base + tg];  bl[j][1] = pBl[base + tg + 4];
            }
#pragma unroll
            for (int i = 0; i < 4; i++) {
                int base  = (wm * 64 + i * 16 + gid) * SROW + ks * 8;
                int base8 = base + 8 * SROW;
                unsigned ah0 = pAh[base + tg],     ah1 = pAh[base8 + tg];
                unsigned ah2 = pAh[base + tg + 4], ah3 = pAh[base8 + tg + 4];
                unsigned al0 = pAl[base + tg],     al1 = pAl[base8 + tg];
                unsigned al2 = pAl[base + tg + 4], al3 = pAl[base8 + tg + 4];
#pragma unroll
                for (int j = 0; j < 4; j++) {
                    mma16816(c[i][j], ah0, ah1, ah2, ah3, bh[j][0], bh[j][1]);
                    mma16816(c[i][j], ah0, ah1, ah2, ah3, bl[j][0], bl[j][1]);
                    mma16816(c[i][j], al0, al1, al2, al3, bh[j][0], bh[j][1]);
                }
            }
        }
        __syncthreads();
    }

    // ---- epilogue ----
#pragma unroll
    for (int i = 0; i < 4; i++) {
        int m = m0 + wm * 64 + i * 16 + gid;
#pragma unroll
        for (int j = 0; j < 4; j++) {
            int nn = n0 + wn * 32 + j * 8 + tg * 2;
#pragma unroll
            for (int rr = 0; rr < 2; rr++) {
                int mm = m + rr * 8;
#pragma unroll
                for (int cc = 0; cc < 2; cc++) {
                    int nc = nn + cc;
                    if (nc < Nout) {
                        float v = c[i][j][rr * 2 + cc] + bias[nc];
                        if (ACT == 1) v = tanhf(v);
                        Y[(size_t)mm * Nout + nc] = v;
                    }
                }
            }
        }
    }
}

// ---------------------------------------------------------------------------
// One warp per (b, n, h); float2 lanes; writes att as bf16 hi/lo split.
// ---------------------------------------------------------------------------
__global__ void attn_kernel(const float* __restrict__ q,
                            const float* __restrict__ off,
                            const float* __restrict__ kv,
                            __nv_bfloat16* __restrict__ ahi,
                            __nv_bfloat16* __restrict__ alo) {
    int gw   = (blockIdx.x * blockDim.x + threadIdx.x) >> 5;
    int lane = threadIdx.x & 31;
    if (gw >= Bb * Nn * Hh) return;

    int hh = gw & (Hh - 1);
    int n  = (gw >> 3) & (Nn - 1);
    int b  = gw >> 15;

    size_t row = (size_t)(b * Nn + n);
    float2 q2 = *reinterpret_cast<const float2*>(q + row * Dd + hh * HDm + 2 * lane);

    float bx = (float)(n & (GW - 1));
    float by = (float)(n >> 8);

    const float* offp = off + row * (Hh * Pp * 2) + hh * Pp * 2;
    const float* kvb  = kv + (size_t)b * Nn * (2 * Dd);

    float lg[Pp], sv0[Pp], sv1[Pp];

#pragma unroll
    for (int p = 0; p < Pp; p++) {
        float sx = bx + 4.0f * offp[2 * p];
        float sy = by + 4.0f * offp[2 * p + 1];
        float x0f = floorf(sx), y0f = floorf(sy);
        int   x0 = (int)x0f,  y0 = (int)y0f;
        float wx1 = sx - x0f, wy1 = sy - y0f;
        float wx0 = 1.0f - wx1, wy0 = 1.0f - wy1;

        float sk0 = 0.f, sk1 = 0.f, v0 = 0.f, v1 = 0.f;
#pragma unroll
        for (int cc = 0; cc < 4; cc++) {
            int   xi = x0 + (cc & 1);
            int   yi = y0 + (cc >> 1);
            float wgt = ((cc & 1) ? wx1 : wx0) * ((cc >> 1) ? wy1 : wy0);
            if (xi >= 0 && xi < GW && yi >= 0 && yi < GH) {
                const float* ptr = kvb + (size_t)(yi * GW + xi) * (2 * Dd) + hh * HDm + 2 * lane;
                float2 kk = *reinterpret_cast<const float2*>(ptr);
                float2 vv = *reinterpret_cast<const float2*>(ptr + Dd);
                sk0 = fmaf(wgt, kk.x, sk0);
                sk1 = fmaf(wgt, kk.y, sk1);
                v0  = fmaf(wgt, vv.x, v0);
                v1  = fmaf(wgt, vv.y, v1);
            }
        }
        float d = q2.x * sk0 + q2.y * sk1;
#pragma unroll
        for (int s = 16; s > 0; s >>= 1)
            d += __shfl_xor_sync(0xffffffffu, d, s);
        lg[p]  = d * 0.125f;
        sv0[p] = v0;
        sv1[p] = v1;
    }

    float mx = lg[0];
#pragma unroll
    for (int p = 1; p < Pp; p++) mx = fmaxf(mx, lg[p]);
    float se = 0.f, wp[Pp];
#pragma unroll
    for (int p = 0; p < Pp; p++) { wp[p] = __expf(lg[p] - mx); se += wp[p]; }
    float inv = 1.0f / se;

    float o0 = 0.f, o1 = 0.f;
#pragma unroll
    for (int p = 0; p < Pp; p++) { o0 = fmaf(wp[p], sv0[p], o0); o1 = fmaf(wp[p], sv1[p], o1); }
    o0 *= inv; o1 *= inv;

    // split to bf16 hi/lo and store packed
    size_t oidx = row * Dd + hh * HDm + 2 * lane;
    __nv_bfloat16 h0 = __float2bfloat16(o0);
    __nv_bfloat16 h1 = __float2bfloat16(o1);
    __nv_bfloat16 l0 = __float2bfloat16(o0 - __bfloat162float(h0));
    __nv_bfloat16 l1 = __float2bfloat16(o1 - __bfloat162float(h1));
    *reinterpret_cast<__nv_bfloat162*>(ahi + oidx) = __halves2bfloat162(h0, h1);
    *reinterpret_cast<__nv_bfloat162*>(alo + oidx) = __halves2bfloat162(l0, l1);
}

// ---------------------------------------------------------------------------
extern "C" void kernel_launch(void* const* d_in, const int* in_sizes, int n_in,
                              void* d_out, int out_size) {
    const float* x    = (const float*)d_in[0];
    const float* Wq   = (const float*)d_in[1];
    const float* bq   = (const float*)d_in[2];
    const float* Woff = (const float*)d_in[3];
    const float* boff = (const float*)d_in[4];
    const float* Wkv  = (const float*)d_in[5];
    const float* bkv  = (const float*)d_in[6];
    const float* Wo   = (const float*)d_in[7];
    const float* bo   = (const float*)d_in[8];
    float* out = (float*)d_out;

    float *qb, *offb, *kvb;
    __nv_bfloat16 *xhi, *xlo, *wqhi, *wqlo, *wfhi, *wflo, *wkhi, *wklo, *wohi, *wolo, *ahi, *alo;
    cudaGetSymbolAddress((void**)&qb,   g_q);
    cudaGetSymbolAddress((void**)&offb, g_off);
    cudaGetSymbolAddress((void**)&kvb,  g_kv);
    cudaGetSymbolAddress((void**)&xhi,  g_xhi);  cudaGetSymbolAddress((void**)&xlo,  g_xlo);
    cudaGetSymbolAddress((void**)&wqhi, g_wqhi); cudaGetSymbolAddress((void**)&wqlo, g_wqlo);
    cudaGetSymbolAddress((void**)&wfhi, g_wfhi); cudaGetSymbolAddress((void**)&wflo, g_wflo);
    cudaGetSymbolAddress((void**)&wkhi, g_wkhi); cudaGetSymbolAddress((void**)&wklo, g_wklo);
    cudaGetSymbolAddress((void**)&wohi, g_wohi); cudaGetSymbolAddress((void**)&wolo, g_wolo);
    cudaGetSymbolAddress((void**)&ahi,  g_ahi);  cudaGetSymbolAddress((void**)&alo,  g_alo);

    // one-time per-launch conversions (fp32 -> bf16 hi/lo)
    auto cvt = [&](const float* s, __nv_bfloat16* h, __nv_bfloat16* l, int ns, int nd) {
        convert_split<<<(nd + 255) / 256, 256>>>(s, h, l, ns, nd);
    };
    cvt(x,    xhi,  xlo,  Mrows * Kdim, Mrows * Kdim);
    cvt(Wq,   wqhi, wqlo, 512 * Kdim,   512 * Kdim);
    cvt(Woff, wfhi, wflo, 144 * Kdim,   256 * Kdim);   // zero-padded
    cvt(Wkv,  wkhi, wklo, 1024 * Kdim,  1024 * Kdim);
    cvt(Wo,   wohi, wolo, 512 * Kdim,   512 * Kdim);

    const int smem = 8 * STAGE_W * 4;   // 80 KB
    cudaFuncSetAttribute(gemm_pre<0>, cudaFuncAttributeMaxDynamicSharedMemorySize, smem);
    cudaFuncSetAttribute(gemm_pre<1>, cudaFuncAttributeMaxDynamicSharedMemorySize, smem);

    // q = x @ Wq^T + bq
    gemm_pre<0><<<dim3(4, Mrows / 128), 256, smem>>>(xhi, xlo, wqhi, wqlo, bq, qb, 512);
    // off = tanh(x @ Woff^T + boff)
    gemm_pre<1><<<dim3(2, Mrows / 128), 256, smem>>>(xhi, xlo, wfhi, wflo, boff, offb, 144);
    // kv = x @ Wkv^T + bkv
    gemm_pre<0><<<dim3(8, Mrows / 128), 256, smem>>>(xhi, xlo, wkhi, wklo, bkv, kvb, 1024);

    // deformable sampling + attention (writes bf16 hi/lo att)
    int total_warps = Bb * Nn * Hh;
    attn_kernel<<<total_warps / 4, 128>>>(qb, offb, kvb, ahi, alo);

    // out = att @ Wo^T + bo  -> d_out (fp32)
    gemm_pre<0><<<dim3(4, Mrows / 128), 256, smem>>>(ahi, alo, wohi, wolo, bo, out, 512);
}

// round 5
// speedup vs baseline: 3.8561x; 1.4561x over previous
#include <cuda_runtime.h>
#include <cuda_bf16.h>
#include <math.h>
#include <stdint.h>

// Problem constants
#define Bb 2
#define Nn 4096
#define Dd 512
#define Hh 8
#define Pp 9
#define GW 256
#define GH 16
#define Mrows 8192
#define Kdim 512
#define NT 16              // k-tiles of 32
#define NCAT 1792          // 512(q) + 1024(kv) + 256(off padded)

// ---------------- scratch (device globals) ----------------
__device__ float g_q  [Mrows * Dd];
__device__ float g_off[Mrows * Hh * Pp * 2];
__device__ float g_kv [Mrows * 2 * Dd];
__device__ float g_bcat[NCAT];
__device__ __nv_bfloat16 g_xhi[Mrows * Kdim], g_xlo[Mrows * Kdim];
__device__ __nv_bfloat16 g_wcathi[NCAT * Kdim], g_wcatlo[NCAT * Kdim];
__device__ __nv_bfloat16 g_wohi[512 * Kdim],  g_wolo[512 * Kdim];
__device__ __nv_bfloat16 g_ahi[Mrows * Kdim], g_alo[Mrows * Kdim];

// ---------------- helpers ----------------
__device__ __forceinline__ uint32_t smem_u32(const void* p) {
    uint32_t a;
    asm("{ .reg .u64 t; cvta.to.shared.u64 t, %1; cvt.u32.u64 %0, t; }" : "=r"(a) : "l"(p));
    return a;
}
__device__ __forceinline__ void cpa16(uint32_t dst, const void* g) {
    asm volatile("cp.async.cg.shared.global [%0], [%1], 16;" :: "r"(dst), "l"(g));
}
#define LDSM4(r, a) \
    asm volatile("ldmatrix.sync.aligned.m8n8.x4.shared.b16 {%0,%1,%2,%3}, [%4];" \
        : "=r"((r)[0]), "=r"((r)[1]), "=r"((r)[2]), "=r"((r)[3]) : "r"(a))

__device__ __forceinline__ void mma16816(float c[4],
        const uint32_t a[4], uint32_t b0, uint32_t b1) {
    asm volatile(
        "mma.sync.aligned.m16n8k16.row.col.f32.bf16.bf16.f32 "
        "{%0,%1,%2,%3},{%4,%5,%6,%7},{%8,%9},{%0,%1,%2,%3};"
        : "+f"(c[0]), "+f"(c[1]), "+f"(c[2]), "+f"(c[3])
        : "r"(a[0]), "r"(a[1]), "r"(a[2]), "r"(a[3]), "r"(b0), "r"(b1));
}

// swizzled smem byte offset within an 8KB plane (128 rows x 64B)
__device__ __forceinline__ uint32_t swz(int row, int c) {
    return (uint32_t)(row * 64 + ((c ^ ((row >> 1) & 3)) << 4));
}

// ---------------- fp32 -> bf16 hi/lo (plain row-major planes) ---------------
__global__ void convert_split(const float* __restrict__ src,
                              __nv_bfloat16* __restrict__ hi,
                              __nv_bfloat16* __restrict__ lo,
                              int rows_src, int rows_dst, int dst_off) {
    int i = blockIdx.x * blockDim.x + threadIdx.x;          // pair index
    if (i >= rows_dst * (Kdim / 2)) return;
    int m = i / (Kdim / 2), k = (i % (Kdim / 2)) * 2;
    float2 v = (m < rows_src) ? *reinterpret_cast<const float2*>(src + (size_t)m * Kdim + k)
                              : make_float2(0.f, 0.f);
    __nv_bfloat16 h0 = __float2bfloat16(v.x), h1 = __float2bfloat16(v.y);
    __nv_bfloat16 l0 = __float2bfloat16(v.x - __bfloat162float(h0));
    __nv_bfloat16 l1 = __float2bfloat16(v.y - __bfloat162float(h1));
    size_t o = (size_t)(dst_off + m) * Kdim + k;
    *reinterpret_cast<__nv_bfloat162*>(hi + o) = __halves2bfloat162(h0, h1);
    *reinterpret_cast<__nv_bfloat162*>(lo + o) = __halves2bfloat162(l0, l1);
}

__global__ void concat_bias(const float* bq, const float* bkv, const float* boff,
                            float* bcat) {
    int i = blockIdx.x * blockDim.x + threadIdx.x;
    if (i >= NCAT) return;
    float v = 0.f;
    if (i < 512) v = bq[i];
    else if (i < 1536) v = bkv[i - 512];
    else if (i < 1680) v = boff[i - 1536];
    bcat[i] = v;
}

// ---------------------------------------------------------------------------
// GEMM: C[M, N] = A[M,512] @ B[Nb,512]^T (+bias). bf16 hi/lo split (3 MMAs).
// Block 128x128, BK=32, 3-stage cp.async, 256 thr (8 warps, 2M x 4N).
// MODE 0: fused x-GEMM, routes output to q/kv/off (tanh on off region).
// MODE 1: plain output to Y (Nout=512).
// ---------------------------------------------------------------------------
#define STAGE_B 32768
#define SMEMSZ  (3 * STAGE_B)

template <int MODE>
__global__ __launch_bounds__(256, 2) void gemm_mma(
        const __nv_bfloat16* __restrict__ Ahi, const __nv_bfloat16* __restrict__ Alo,
        const __nv_bfloat16* __restrict__ Bhi, const __nv_bfloat16* __restrict__ Blo,
        const float* __restrict__ bias, float* __restrict__ Y,
        float* __restrict__ q_out, float* __restrict__ kv_out, float* __restrict__ off_out) {
    extern __shared__ char smem[];
    const uint32_t sb = smem_u32(smem);

    const int t    = threadIdx.x;
    const int m0   = blockIdx.y * 128;
    const int n0   = blockIdx.x * 128;
    const int wid  = t >> 5;
    const int lane = t & 31;
    const int gid  = lane >> 2;
    const int tg   = lane & 3;
    const int wm   = wid & 1;
    const int wn   = wid >> 1;

    float c[4][4][4] = {};

    // cp.async stage loader: 8 chunks/thread (4 planes x 512 chunks)
    auto issue = [&](int kt) {
        const uint32_t stg = sb + (kt % 3) * STAGE_B;
#pragma unroll
        for (int qq = 0; qq < 8; qq++) {
            const int plane = qq >> 1;
            const int idx = ((qq & 1) << 8) + t;
            const int row = idx >> 2, cc = idx & 3;
            const __nv_bfloat16* g =
                (plane == 0) ? Ahi : (plane == 1) ? Alo : (plane == 2) ? Bhi : Blo;
            const int grow = ((plane < 2) ? m0 : n0) + row;
            cpa16(stg + plane * 8192 + swz(row, cc),
                  g + (size_t)grow * Kdim + kt * 32 + cc * 8);
        }
        asm volatile("cp.async.commit_group;");
    };

    issue(0); issue(1); issue(2);

    // fragment addresses (depend only on lane)
    const int aRow = wm * 64 + ((lane >> 3) & 1) * 8 + (lane & 7);   // + i*16
    const int aCb  = (lane >> 4) & 1;                                // + ks*2
    const int bRow = wn * 32 + ((lane >> 4) & 1) * 8 + (lane & 7);   // + jj*16
    const int bCb  = (lane >> 3) & 1;                                // + ks*2

    for (int kt = 0; kt < NT; kt++) {
        asm volatile("cp.async.wait_group 2;");
        __syncthreads();
        const uint32_t stg = sb + (kt % 3) * STAGE_B;
        const uint32_t pAh = stg, pAl = stg + 8192, pBh = stg + 16384, pBl = stg + 24576;

#pragma unroll
        for (int ks = 0; ks < 2; ks++) {
            uint32_t bh[8], bl[8];
#pragma unroll
            for (int jj = 0; jj < 2; jj++) {
                uint32_t off = swz(bRow + jj * 16, ks * 2 + bCb);
                LDSM4(&bh[jj * 4], pBh + off);
                LDSM4(&bl[jj * 4], pBl + off);
            }
#pragma unroll
            for (int i = 0; i < 4; i++) {
                uint32_t ah[4], al[4];
                uint32_t off = swz(aRow + i * 16, ks * 2 + aCb);
                LDSM4(ah, pAh + off);
                LDSM4(al, pAl + off);
#pragma unroll
                for (int j = 0; j < 4; j++) {
                    mma16816(c[i][j], ah, bh[j * 2], bh[j * 2 + 1]);
                    mma16816(c[i][j], ah, bl[j * 2], bl[j * 2 + 1]);
                    mma16816(c[i][j], al, bh[j * 2], bh[j * 2 + 1]);
                }
            }
        }
        __syncthreads();
        if (kt + 3 < NT) issue(kt + 3);
        else asm volatile("cp.async.commit_group;");
    }

    // ---- epilogue ----
#pragma unroll
    for (int i = 0; i < 4; i++) {
        const int m = m0 + wm * 64 + i * 16 + gid;
#pragma unroll
        for (int j = 0; j < 4; j++) {
            const int ng = n0 + wn * 32 + j * 8 + tg * 2;
            float b0 = bias[ng], b1 = bias[ng + 1];
            float v00 = c[i][j][0] + b0, v01 = c[i][j][1] + b1;
            float v10 = c[i][j][2] + b0, v11 = c[i][j][3] + b1;
            if (MODE == 1) {
                *reinterpret_cast<float2*>(Y + (size_t)m * 512 + ng)       = make_float2(v00, v01);
                *reinterpret_cast<float2*>(Y + (size_t)(m + 8) * 512 + ng) = make_float2(v10, v11);
            } else {
                if (ng < 512) {
                    *reinterpret_cast<float2*>(q_out + (size_t)m * 512 + ng)       = make_float2(v00, v01);
                    *reinterpret_cast<float2*>(q_out + (size_t)(m + 8) * 512 + ng) = make_float2(v10, v11);
                } else if (ng < 1536) {
                    int cc = ng - 512;
                    *reinterpret_cast<float2*>(kv_out + (size_t)m * 1024 + cc)       = make_float2(v00, v01);
                    *reinterpret_cast<float2*>(kv_out + (size_t)(m + 8) * 1024 + cc) = make_float2(v10, v11);
                } else {
                    int cc = ng - 1536;
                    if (cc < 144) {
                        *reinterpret_cast<float2*>(off_out + (size_t)m * 144 + cc) =
                            make_float2(tanhf(v00), tanhf(v01));
                        *reinterpret_cast<float2*>(off_out + (size_t)(m + 8) * 144 + cc) =
                            make_float2(tanhf(v10), tanhf(v11));
                    }
                }
            }
        }
    }
}

// ---------------- deformable sampling + attention ----------------
// One warp per (b,n,h). Lanes 0-15 own k dims (4 each), lanes 16-31 own v dims.
__global__ void attn_kernel(const float* __restrict__ q,
                            const float* __restrict__ off,
                            const float* __restrict__ kv,
                            __nv_bfloat16* __restrict__ ahi,
                            __nv_bfloat16* __restrict__ alo) {
    int gw   = (blockIdx.x * blockDim.x + threadIdx.x) >> 5;
    int lane = threadIdx.x & 31;
    if (gw >= Bb * Nn * Hh) return;

    int hh = gw & 7;
    int n  = (gw >> 3) & 4095;
    int b  = gw >> 15;
    size_t row = (size_t)(b * Nn + n);

    const bool isK = lane < 16;
    const int d4 = (lane & 15) * 4;

    float4 q4 = make_float4(0.f, 0.f, 0.f, 0.f);
    if (isK) q4 = *reinterpret_cast<const float4*>(q + row * Dd + hh * 64 + d4);

    float bx = (float)(n & 255);
    float by = (float)(n >> 8);
    const float* offp = off + row * (Hh * Pp * 2) + hh * Pp * 2;
    const float* kvb  = kv + (size_t)b * Nn * 1024;
    const int laneoff = (isK ? 0 : 512) + hh * 64 + d4;

    float lg[Pp];
    float4 sv[Pp];

#pragma unroll
    for (int p = 0; p < Pp; p++) {
        float sx = bx + 4.0f * offp[2 * p];
        float sy = by + 4.0f * offp[2 * p + 1];
        float x0f = floorf(sx), y0f = floorf(sy);
        int   x0 = (int)x0f,  y0 = (int)y0f;
        float wx1 = sx - x0f, wy1 = sy - y0f;
        float wx0 = 1.0f - wx1, wy0 = 1.0f - wy1;

        float4 acc = make_float4(0.f, 0.f, 0.f, 0.f);
#pragma unroll
        for (int cc = 0; cc < 4; cc++) {
            int   xi = x0 + (cc & 1);
            int   yi = y0 + (cc >> 1);
            float wg = ((cc & 1) ? wx1 : wx0) * ((cc >> 1) ? wy1 : wy0);
            if (xi >= 0 && xi < GW && yi >= 0 && yi < GH) {
                float4 tv = *reinterpret_cast<const float4*>(
                    kvb + (size_t)(yi * GW + xi) * 1024 + laneoff);
                acc.x = fmaf(wg, tv.x, acc.x);
                acc.y = fmaf(wg, tv.y, acc.y);
                acc.z = fmaf(wg, tv.z, acc.z);
                acc.w = fmaf(wg, tv.w, acc.w);
            }
        }
        float d = isK ? (q4.x * acc.x + q4.y * acc.y + q4.z * acc.z + q4.w * acc.w) : 0.f;
#pragma unroll
        for (int s = 16; s > 0; s >>= 1)
            d += __shfl_xor_sync(0xffffffffu, d, s);
        lg[p] = d * 0.125f;
        sv[p] = acc;
    }

    float mx = lg[0];
#pragma unroll
    for (int p = 1; p < Pp; p++) mx = fmaxf(mx, lg[p]);
    float se = 0.f, wp[Pp];
#pragma unroll
    for (int p = 0; p < Pp; p++) { wp[p] = __expf(lg[p] - mx); se += wp[p]; }
    float inv = 1.0f / se;

    float4 o = make_float4(0.f, 0.f, 0.f, 0.f);
#pragma unroll
    for (int p = 0; p < Pp; p++) {
        o.x = fmaf(wp[p], sv[p].x, o.x);
        o.y = fmaf(wp[p], sv[p].y, o.y);
        o.z = fmaf(wp[p], sv[p].z, o.z);
        o.w = fmaf(wp[p], sv[p].w, o.w);
    }

    if (!isK) {
        o.x *= inv; o.y *= inv; o.z *= inv; o.w *= inv;
        size_t addr = row * Dd + hh * 64 + d4;
        __nv_bfloat16 h0 = __float2bfloat16(o.x), h1 = __float2bfloat16(o.y);
        __nv_bfloat16 h2 = __float2bfloat16(o.z), h3 = __float2bfloat16(o.w);
        __nv_bfloat16 l0 = __float2bfloat16(o.x - __bfloat162float(h0));
        __nv_bfloat16 l1 = __float2bfloat16(o.y - __bfloat162float(h1));
        __nv_bfloat16 l2 = __float2bfloat16(o.z - __bfloat162float(h2));
        __nv_bfloat16 l3 = __float2bfloat16(o.w - __bfloat162float(h3));
        reinterpret_cast<__nv_bfloat162*>(ahi + addr)[0] = __halves2bfloat162(h0, h1);
        reinterpret_cast<__nv_bfloat162*>(ahi + addr)[1] = __halves2bfloat162(h2, h3);
        reinterpret_cast<__nv_bfloat162*>(alo + addr)[0] = __halves2bfloat162(l0, l1);
        reinterpret_cast<__nv_bfloat162*>(alo + addr)[1] = __halves2bfloat162(l2, l3);
    }
}

// ---------------------------------------------------------------------------
extern "C" void kernel_launch(void* const* d_in, const int* in_sizes, int n_in,
                              void* d_out, int out_size) {
    const float* x    = (const float*)d_in[0];
    const float* Wq   = (const float*)d_in[1];
    const float* bq   = (const float*)d_in[2];
    const float* Woff = (const float*)d_in[3];
    const float* boff = (const float*)d_in[4];
    const float* Wkv  = (const float*)d_in[5];
    const float* bkv  = (const float*)d_in[6];
    const float* Wo   = (const float*)d_in[7];
    const float* bo   = (const float*)d_in[8];
    float* out = (float*)d_out;

    float *qb, *offb, *kvb, *bcat;
    __nv_bfloat16 *xhi, *xlo, *wchi, *wclo, *wohi, *wolo, *ahi, *alo;
    cudaGetSymbolAddress((void**)&qb,   g_q);
    cudaGetSymbolAddress((void**)&offb, g_off);
    cudaGetSymbolAddress((void**)&kvb,  g_kv);
    cudaGetSymbolAddress((void**)&bcat, g_bcat);
    cudaGetSymbolAddress((void**)&xhi,  g_xhi);    cudaGetSymbolAddress((void**)&xlo,  g_xlo);
    cudaGetSymbolAddress((void**)&wchi, g_wcathi); cudaGetSymbolAddress((void**)&wclo, g_wcatlo);
    cudaGetSymbolAddress((void**)&wohi, g_wohi);   cudaGetSymbolAddress((void**)&wolo, g_wolo);
    cudaGetSymbolAddress((void**)&ahi,  g_ahi);    cudaGetSymbolAddress((void**)&alo,  g_alo);

    auto cvt = [&](const float* s, __nv_bfloat16* h, __nv_bfloat16* l,
                   int rs, int rd, int off) {
        convert_split<<<(rd * (Kdim / 2) + 255) / 256, 256>>>(s, h, l, rs, rd, off);
    };
    cvt(x,    xhi,  xlo,  8192, 8192, 0);
    cvt(Wq,   wchi, wclo, 512,  512,  0);
    cvt(Wkv,  wchi, wclo, 1024, 1024, 512);
    cvt(Woff, wchi, wclo, 144,  256,  1536);
    cvt(Wo,   wohi, wolo, 512,  512,  0);
    concat_bias<<<(NCAT + 255) / 256, 256>>>(bq, bkv, boff, bcat);

    cudaFuncSetAttribute(gemm_mma<0>, cudaFuncAttributeMaxDynamicSharedMemorySize, SMEMSZ);
    cudaFuncSetAttribute(gemm_mma<1>, cudaFuncAttributeMaxDynamicSharedMemorySize, SMEMSZ);

    // fused: [q | kv | off] = x @ Wcat^T + bcat  (tanh on off region)
    gemm_mma<0><<<dim3(NCAT / 128, Mrows / 128), 256, SMEMSZ>>>(
        xhi, xlo, wchi, wclo, bcat, nullptr, qb, kvb, offb);

    // deformable sampling + attention (writes att hi/lo planes)
    attn_kernel<<<(Bb * Nn * Hh) / 4, 128>>>(qb, offb, kvb, ahi, alo);

    // out = att @ Wo^T + bo -> d_out
    gemm_mma<1><<<dim3(4, Mrows / 128), 256, SMEMSZ>>>(
        ahi, alo, wohi, wolo, bo, out, nullptr, nullptr, nullptr);
}

// round 7
// speedup vs baseline: 4.2267x; 1.0961x over previous
#include <cuda_runtime.h>
#include <cuda_fp16.h>
#include <math.h>
#include <stdint.h>

// Problem constants
#define Bb 2
#define Nn 4096
#define Dd 512
#define Hh 8
#define Pp 9
#define GW 256
#define GH 16
#define Mrows 8192
#define Kdim 512
#define NT 16              // k-tiles of 32
#define NCAT 1792          // 512(q) + 1024(kv) + 256(off padded)

#define LAM    0.015625f   // 2^-6
#define LAMINV 64.0f
#define ONE_M_LAM 0.984375f

// ---------------- scratch (device globals) ----------------
__device__ float g_q  [Mrows * Dd];
__device__ float g_off[Mrows * Hh * Pp * 2];
__device__ float g_kv [Mrows * 2 * Dd];
__device__ float g_bcat[NCAT];
__device__ __half g_xh[Mrows * Kdim], g_x2[Mrows * Kdim];
__device__ __half g_wch[NCAT * Kdim], g_wc2[NCAT * Kdim];
__device__ __half g_woh[512 * Kdim],  g_wo2[512 * Kdim];
__device__ __half g_ah[Mrows * Kdim], g_a2[Mrows * Kdim];

// ---------------- helpers ----------------
__device__ __forceinline__ uint32_t smem_u32(const void* p) {
    uint32_t a;
    asm("{ .reg .u64 t; cvta.to.shared.u64 t, %1; cvt.u32.u64 %0, t; }" : "=r"(a) : "l"(p));
    return a;
}
__device__ __forceinline__ void cpa16(uint32_t dst, const void* g) {
    asm volatile("cp.async.cg.shared.global [%0], [%1], 16;" :: "r"(dst), "l"(g));
}
#define LDSM4(r, a) \
    asm volatile("ldmatrix.sync.aligned.m8n8.x4.shared.b16 {%0,%1,%2,%3}, [%4];" \
        : "=r"((r)[0]), "=r"((r)[1]), "=r"((r)[2]), "=r"((r)[3]) : "r"(a))

__device__ __forceinline__ void mma16816(float c[4],
        const uint32_t a[4], uint32_t b0, uint32_t b1) {
    asm volatile(
        "mma.sync.aligned.m16n8k16.row.col.f32.f16.f16.f32 "
        "{%0,%1,%2,%3},{%4,%5,%6,%7},{%8,%9},{%0,%1,%2,%3};"
        : "+f"(c[0]), "+f"(c[1]), "+f"(c[2]), "+f"(c[3])
        : "r"(a[0]), "r"(a[1]), "r"(a[2]), "r"(a[3]), "r"(b0), "r"(b1));
}

// swizzled smem byte offset within an 8KB plane (128 rows x 64B)
__device__ __forceinline__ uint32_t swz(int row, int c) {
    return (uint32_t)(row * 64 + ((c ^ ((row >> 1) & 3)) << 4));
}

// lambda-split pair: h = fl16(v); p2 = fl16(LAM*h + (v - h))
__device__ __forceinline__ void lam_split_a(float v, __half& h, __half& p2) {
    h = __float2half(v);
    float hf = __half2float(h);
    p2 = __float2half(fmaf(LAM, hf, v - hf));
}
// weight-side: h = fl16(v); p2 = fl16(h + LAMINV*(v - h))
__device__ __forceinline__ void lam_split_b(float v, __half& h, __half& p2) {
    h = __float2half(v);
    float hf = __half2float(h);
    p2 = __float2half(fmaf(LAMINV, v - hf, hf));
}

// ---------------- converts ----------------
__global__ void convert_a(const float* __restrict__ src,
                          __half* __restrict__ Ph, __half* __restrict__ P2,
                          int total_pairs) {
    int i = blockIdx.x * blockDim.x + threadIdx.x;
    if (i >= total_pairs) return;
    float2 v = reinterpret_cast<const float2*>(src)[i];
    __half h0, h1, p0, p1;
    lam_split_a(v.x, h0, p0);
    lam_split_a(v.y, h1, p1);
    reinterpret_cast<__half2*>(Ph)[i] = __halves2half2(h0, h1);
    reinterpret_cast<__half2*>(P2)[i] = __halves2half2(p0, p1);
}

__global__ void convert_b(const float* __restrict__ src,
                          __half* __restrict__ Ph, __half* __restrict__ P2,
                          int rows_src, int rows_dst, int dst_off) {
    int i = blockIdx.x * blockDim.x + threadIdx.x;
    if (i >= rows_dst * (Kdim / 2)) return;
    int m = i / (Kdim / 2), k = (i % (Kdim / 2)) * 2;
    float2 v = (m < rows_src) ? *reinterpret_cast<const float2*>(src + (size_t)m * Kdim + k)
                              : make_float2(0.f, 0.f);
    __half h0, h1, p0, p1;
    lam_split_b(v.x, h0, p0);
    lam_split_b(v.y, h1, p1);
    size_t o = ((size_t)(dst_off + m) * Kdim + k) >> 1;
    reinterpret_cast<__half2*>(Ph)[o] = __halves2half2(h0, h1);
    reinterpret_cast<__half2*>(P2)[o] = __halves2half2(p0, p1);
}

__global__ void concat_bias(const float* bq, const float* bkv, const float* boff,
                            float* bcat) {
    int i = blockIdx.x * blockDim.x + threadIdx.x;
    if (i >= NCAT) return;
    float v = 0.f;
    if (i < 512) v = bq[i];
    else if (i < 1536) v = bkv[i - 512];
    else if (i < 1680) v = boff[i - 1536];
    bcat[i] = v;
}

// ---------------------------------------------------------------------------
// GEMM via lambda-compensated 2-term fp16 split:
//   C = (1-LAM)*(Ah @ Bh^T) + (A2 @ B2^T) + bias
// Block 128x128, BK=32, 3-stage cp.async, 512 thr (16 warps, 4M x 4N),
// warp tile 32x32 (2 m-tiles x 4 n-tiles), dual accumulators.
// MODE 0: fused x-GEMM routing to q/kv/off (tanh on off). MODE 1: plain Y.
// ---------------------------------------------------------------------------
#define STAGE_B 32768
#define SMEMSZ  (3 * STAGE_B)

template <int MODE>
__global__ __launch_bounds__(512, 1) void gemm_mma(
        const __half* __restrict__ Ah, const __half* __restrict__ A2,
        const __half* __restrict__ Bh, const __half* __restrict__ B2,
        const float* __restrict__ bias, float* __restrict__ Y,
        float* __restrict__ q_out, float* __restrict__ kv_out, float* __restrict__ off_out) {
    extern __shared__ char smem[];
    const uint32_t sb = smem_u32(smem);

    const int t    = threadIdx.x;
    const int m0   = blockIdx.y * 128;
    const int n0   = blockIdx.x * 128;
    const int wid  = t >> 5;
    const int lane = t & 31;
    const int gid  = lane >> 2;
    const int tg   = lane & 3;
    const int wm   = wid & 3;     // 4 warps in M
    const int wn   = wid >> 2;    // 4 warps in N

    float c1[2][4][4] = {};
    float c2[2][4][4] = {};

    // cp.async: 4 planes x 512 chunks of 16B; 4 chunks/thread
    const int lrow = t >> 2, lcc = t & 3;
    auto issue = [&](int kt) {
        const uint32_t stg = sb + (kt % 3) * STAGE_B;
#pragma unroll
        for (int plane = 0; plane < 4; plane++) {
            const __half* g = (plane == 0) ? Ah : (plane == 1) ? A2
                            : (plane == 2) ? Bh : B2;
            const int grow = ((plane < 2) ? m0 : n0) + lrow;
            cpa16(stg + plane * 8192 + swz(lrow, lcc),
                  g + (size_t)grow * Kdim + kt * 32 + lcc * 8);
        }
        asm volatile("cp.async.commit_group;");
    };

    issue(0); issue(1); issue(2);

    // fragment addressing (lane-only)
    const int aRow = wm * 32 + ((lane >> 3) & 1) * 8 + (lane & 7);   // + i*16
    const int aCb  = (lane >> 4) & 1;                                // + ks*2
    const int bRow = wn * 32 + ((lane >> 4) & 1) * 8 + (lane & 7);   // + jj*16
    const int bCb  = (lane >> 3) & 1;                                // + ks*2

    for (int kt = 0; kt < NT; kt++) {
        asm volatile("cp.async.wait_group 2;");
        __syncthreads();
        const uint32_t stg = sb + (kt % 3) * STAGE_B;
        const uint32_t pAh = stg, pA2 = stg + 8192, pBh = stg + 16384, pB2 = stg + 24576;

#pragma unroll
        for (int ks = 0; ks < 2; ks++) {
            uint32_t bh[8], b2[8];
#pragma unroll
            for (int jj = 0; jj < 2; jj++) {
                uint32_t off = swz(bRow + jj * 16, ks * 2 + bCb);
                LDSM4(&bh[jj * 4], pBh + off);
                LDSM4(&b2[jj * 4], pB2 + off);
            }
#pragma unroll
            for (int i = 0; i < 2; i++) {
                uint32_t ah[4], a2r[4];
                uint32_t off = swz(aRow + i * 16, ks * 2 + aCb);
                LDSM4(ah,  pAh + off);
                LDSM4(a2r, pA2 + off);
#pragma unroll
                for (int j = 0; j < 4; j++) {
                    mma16816(c1[i][j], ah,  bh[j * 2], bh[j * 2 + 1]);
                    mma16816(c2[i][j], a2r, b2[j * 2], b2[j * 2 + 1]);
                }
            }
        }
        __syncthreads();
        if (kt + 3 < NT) issue(kt + 3);
        else asm volatile("cp.async.commit_group;");
    }

    // ---- epilogue: v = (1-LAM)*c1 + c2 + bias ----
#pragma unroll
    for (int i = 0; i < 2; i++) {
        const int m = m0 + wm * 32 + i * 16 + gid;
#pragma unroll
        for (int j = 0; j < 4; j++) {
            const int ng = n0 + wn * 32 + j * 8 + tg * 2;
            float b0 = bias[ng], b1 = bias[ng + 1];
            float v00 = fmaf(ONE_M_LAM, c1[i][j][0], c2[i][j][0]) + b0;
            float v01 = fmaf(ONE_M_LAM, c1[i][j][1], c2[i][j][1]) + b1;
            float v10 = fmaf(ONE_M_LAM, c1[i][j][2], c2[i][j][2]) + b0;
            float v11 = fmaf(ONE_M_LAM, c1[i][j][3], c2[i][j][3]) + b1;
            if (MODE == 1) {
                *reinterpret_cast<float2*>(Y + (size_t)m * 512 + ng)       = make_float2(v00, v01);
                *reinterpret_cast<float2*>(Y + (size_t)(m + 8) * 512 + ng) = make_float2(v10, v11);
            } else {
                if (ng < 512) {
                    *reinterpret_cast<float2*>(q_out + (size_t)m * 512 + ng)       = make_float2(v00, v01);
                    *reinterpret_cast<float2*>(q_out + (size_t)(m + 8) * 512 + ng) = make_float2(v10, v11);
                } else if (ng < 1536) {
                    int cc = ng - 512;
                    *reinterpret_cast<float2*>(kv_out + (size_t)m * 1024 + cc)       = make_float2(v00, v01);
                    *reinterpret_cast<float2*>(kv_out + (size_t)(m + 8) * 1024 + cc) = make_float2(v10, v11);
                } else {
                    int cc = ng - 1536;
                    if (cc < 144) {
                        *reinterpret_cast<float2*>(off_out + (size_t)m * 144 + cc) =
                            make_float2(tanhf(v00), tanhf(v01));
                        *reinterpret_cast<float2*>(off_out + (size_t)(m + 8) * 144 + cc) =
                            make_float2(tanhf(v10), tanhf(v11));
                    }
                }
            }
        }
    }
}

// ---------------- deformable sampling + attention ----------------
// One warp per (b,n,h). Lanes 0-15 own k dims (4 each), lanes 16-31 own v dims.
__global__ void attn_kernel(const float* __restrict__ q,
                            const float* __restrict__ off,
                            const float* __restrict__ kv,
                            __half* __restrict__ ah,
                            __half* __restrict__ a2) {
    int gw   = (blockIdx.x * blockDim.x + threadIdx.x) >> 5;
    int lane = threadIdx.x & 31;
    if (gw >= Bb * Nn * Hh) return;

    int hh = gw & 7;
    int n  = (gw >> 3) & 4095;
    int b  = gw >> 15;
    size_t row = (size_t)(b * Nn + n);

    const bool isK = lane < 16;
    const int d4 = (lane & 15) * 4;

    float4 q4 = make_float4(0.f, 0.f, 0.f, 0.f);
    if (isK) q4 = *reinterpret_cast<const float4*>(q + row * Dd + hh * 64 + d4);

    float bx = (float)(n & 255);
    float by = (float)(n >> 8);
    const float* offp = off + row * (Hh * Pp * 2) + hh * Pp * 2;
    const float* kvb  = kv + (size_t)b * Nn * 1024;
    const int laneoff = (isK ? 0 : 512) + hh * 64 + d4;

    float lg[Pp];
    float4 sv[Pp];

#pragma unroll
    for (int p = 0; p < Pp; p++) {
        float sx = bx + 4.0f * offp[2 * p];
        float sy = by + 4.0f * offp[2 * p + 1];
        float x0f = floorf(sx), y0f = floorf(sy);
        int   x0 = (int)x0f,  y0 = (int)y0f;
        float wx1 = sx - x0f, wy1 = sy - y0f;
        float wx0 = 1.0f - wx1, wy0 = 1.0f - wy1;

        float4 acc = make_float4(0.f, 0.f, 0.f, 0.f);
#pragma unroll
        for (int cc = 0; cc < 4; cc++) {
            int   xi = x0 + (cc & 1);
            int   yi = y0 + (cc >> 1);
            float wg = ((cc & 1) ? wx1 : wx0) * ((cc >> 1) ? wy1 : wy0);
            if (xi >= 0 && xi < GW && yi >= 0 && yi < GH) {
                float4 tv = *reinterpret_cast<const float4*>(
                    kvb + (size_t)(yi * GW + xi) * 1024 + laneoff);
                acc.x = fmaf(wg, tv.x, acc.x);
                acc.y = fmaf(wg, tv.y, acc.y);
                acc.z = fmaf(wg, tv.z, acc.z);
                acc.w = fmaf(wg, tv.w, acc.w);
            }
        }
        float d = isK ? (q4.x * acc.x + q4.y * acc.y + q4.z * acc.z + q4.w * acc.w) : 0.f;
#pragma unroll
        for (int s = 16; s > 0; s >>= 1)
            d += __shfl_xor_sync(0xffffffffu, d, s);
        lg[p] = d * 0.125f;
        sv[p] = acc;
    }

    float mx = lg[0];
#pragma unroll
    for (int p = 1; p < Pp; p++) mx = fmaxf(mx, lg[p]);
    float se = 0.f, wp[Pp];
#pragma unroll
    for (int p = 0; p < Pp; p++) { wp[p] = __expf(lg[p] - mx); se += wp[p]; }
    float inv = 1.0f / se;

    float4 o = make_float4(0.f, 0.f, 0.f, 0.f);
#pragma unroll
    for (int p = 0; p < Pp; p++) {
        o.x = fmaf(wp[p], sv[p].x, o.x);
        o.y = fmaf(wp[p], sv[p].y, o.y);
        o.z = fmaf(wp[p], sv[p].z, o.z);
        o.w = fmaf(wp[p], sv[p].w, o.w);
    }

    if (!isK) {
        o.x *= inv; o.y *= inv; o.z *= inv; o.w *= inv;
        size_t addr = row * Dd + hh * 64 + d4;
        __half h0, h1, h2, h3, p0, p1, p2, p3;
        lam_split_a(o.x, h0, p0);
        lam_split_a(o.y, h1, p1);
        lam_split_a(o.z, h2, p2);
        lam_split_a(o.w, h3, p3);
        reinterpret_cast<__half2*>(ah + addr)[0] = __halves2half2(h0, h1);
        reinterpret_cast<__half2*>(ah + addr)[1] = __halves2half2(h2, h3);
        reinterpret_cast<__half2*>(a2 + addr)[0] = __halves2half2(p0, p1);
        reinterpret_cast<__half2*>(a2 + addr)[1] = __halves2half2(p2, p3);
    }
}

// ---------------------------------------------------------------------------
extern "C" void kernel_launch(void* const* d_in, const int* in_sizes, int n_in,
                              void* d_out, int out_size) {
    const float* x    = (const float*)d_in[0];
    const float* Wq   = (const float*)d_in[1];
    const float* bq   = (const float*)d_in[2];
    const float* Woff = (const float*)d_in[3];
    const float* boff = (const float*)d_in[4];
    const float* Wkv  = (const float*)d_in[5];
    const float* bkv  = (const float*)d_in[6];
    const float* Wo   = (const float*)d_in[7];
    const float* bo   = (const float*)d_in[8];
    float* out = (float*)d_out;

    float *qb, *offb, *kvb, *bcat;
    __half *xh, *x2, *wch, *wc2, *woh, *wo2, *ah, *a2;
    cudaGetSymbolAddress((void**)&qb,   g_q);
    cudaGetSymbolAddress((void**)&offb, g_off);
    cudaGetSymbolAddress((void**)&kvb,  g_kv);
    cudaGetSymbolAddress((void**)&bcat, g_bcat);
    cudaGetSymbolAddress((void**)&xh,  g_xh);  cudaGetSymbolAddress((void**)&x2,  g_x2);
    cudaGetSymbolAddress((void**)&wch, g_wch); cudaGetSymbolAddress((void**)&wc2, g_wc2);
    cudaGetSymbolAddress((void**)&woh, g_woh); cudaGetSymbolAddress((void**)&wo2, g_wo2);
    cudaGetSymbolAddress((void**)&ah,  g_ah);  cudaGetSymbolAddress((void**)&a2,  g_a2);

    convert_a<<<(Mrows * Kdim / 2 + 255) / 256, 256>>>(x, xh, x2, Mrows * Kdim / 2);
    auto cvtw = [&](const float* s, __half* h, __half* p, int rs, int rd, int off) {
        convert_b<<<(rd * (Kdim / 2) + 255) / 256, 256>>>(s, h, p, rs, rd, off);
    };
    cvtw(Wq,   wch, wc2, 512,  512,  0);
    cvtw(Wkv,  wch, wc2, 1024, 1024, 512);
    cvtw(Woff, wch, wc2, 144,  256,  1536);
    cvtw(Wo,   woh, wo2, 512,  512,  0);
    concat_bias<<<(NCAT + 255) / 256, 256>>>(bq, bkv, boff, bcat);

    cudaFuncSetAttribute(gemm_mma<0>, cudaFuncAttributeMaxDynamicSharedMemorySize, SMEMSZ);
    cudaFuncSetAttribute(gemm_mma<1>, cudaFuncAttributeMaxDynamicSharedMemorySize, SMEMSZ);

    // fused: [q | kv | off] = x @ Wcat^T + bcat (tanh on off region)
    gemm_mma<0><<<dim3(NCAT / 128, Mrows / 128), 512, SMEMSZ>>>(
        xh, x2, wch, wc2, bcat, nullptr, qb, kvb, offb);

    // deformable sampling + attention (writes att hi / lambda planes)
    attn_kernel<<<(Bb * Nn * Hh) / 4, 128>>>(qb, offb, kvb, ah, a2);

    // out = att @ Wo^T + bo -> d_out
    gemm_mma<1><<<dim3(4, Mrows / 128), 512, SMEMSZ>>>(
        ah, a2, woh, wo2, bo, out, nullptr, nullptr, nullptr);
}